// round 14
// baseline (speedup 1.0000x reference)
#include <cuda_runtime.h>
#include <cuda_fp16.h>
#include <cstdint>

// Problem constants
#define BB 8
#define TT 256
#define MM 64
#define DD 512
#define HH 8
#define DKK 64
#define NROWS (BB*TT*MM)        // 131072
#define NBTH  (BB*TT*HH)        // 16384

// Scratch (device globals: allocation-free)
__device__ __half g_xh[(size_t)NROWS*DD];      // X in fp16
__device__ __half g_wqkv[3*DD*DD];             // packed Wq|Wk|Wv fp16 (rows = features)
__device__ __half g_wo[DD*DD];                 // Wo fp16
__device__ __half g_a[(size_t)NROWS*DD];       // (btm, d) fp16 attention output

__device__ __forceinline__ uint32_t smem_u32(const void* p) {
    uint32_t a;
    asm("{ .reg .u64 t; cvta.to.shared.u64 t, %1; cvt.u32.u64 %0, t; }" : "=r"(a) : "l"(p));
    return a;
}
__device__ __forceinline__ void cp16(uint32_t saddr, const void* gaddr) {
    asm volatile("cp.async.cg.shared.global [%0], [%1], 16;" :: "r"(saddr), "l"(gaddr) : "memory");
}
__device__ __forceinline__ void cp_commit() {
    asm volatile("cp.async.commit_group;" ::: "memory");
}

__device__ __forceinline__ void mma_f16(float* c,
    uint32_t a0, uint32_t a1, uint32_t a2, uint32_t a3, uint32_t b0, uint32_t b1)
{
    asm volatile(
        "mma.sync.aligned.m16n8k16.row.col.f32.f16.f16.f32 "
        "{%0,%1,%2,%3}, {%4,%5,%6,%7}, {%8,%9}, {%0,%1,%2,%3};"
        : "+f"(c[0]), "+f"(c[1]), "+f"(c[2]), "+f"(c[3])
        : "r"(a0), "r"(a1), "r"(a2), "r"(a3), "r"(b0), "r"(b1));
}

// ---------------------------------------------------------------------------
// conv kernels: fp32 -> fp16
// ---------------------------------------------------------------------------
__global__ void conv_h(const float4* __restrict__ in, uint2* __restrict__ out, int n4)
{
    int i = blockIdx.x * blockDim.x + threadIdx.x;
    if (i >= n4) return;
    float4 v = in[i];
    __half2 h0 = __floats2half2_rn(v.x, v.y);
    __half2 h1 = __floats2half2_rn(v.z, v.w);
    uint2 r;
    r.x = *(uint32_t*)&h0;
    r.y = *(uint32_t*)&h1;
    out[i] = r;
}

__global__ void conv_w(const float4* __restrict__ wq, const float4* __restrict__ wk,
                       const float4* __restrict__ wv, const float4* __restrict__ wo,
                       uint2* __restrict__ oqkv, uint2* __restrict__ oo)
{
    int i = blockIdx.x * blockDim.x + threadIdx.x;   // 0 .. 4*65536-1
    int t = i >> 16, j = i & 65535;
    const float4* src = (t == 0) ? wq : (t == 1) ? wk : (t == 2) ? wv : wo;
    uint2* dst = (t == 3) ? oo : (oqkv + (size_t)t * (DD*DD/4));
    float4 v = src[j];
    __half2 h0 = __floats2half2_rn(v.x, v.y);
    __half2 h1 = __floats2half2_rn(v.z, v.w);
    uint2 r;
    r.x = *(uint32_t*)&h0;
    r.y = *(uint32_t*)&h1;
    dst[j] = r;
}

// ---------------------------------------------------------------------------
// Fused QKV + attention kernel (R13-proven, + bth0 grid offset).
// One CTA per (bt, h), 128 threads, 3 CTAs/SM.
// ---------------------------------------------------------------------------
#define FSTG 32768
#define FUSED_SMEM (2*FSTG)

__global__ __launch_bounds__(128, 3)
void qkv_attn_kernel(int bth0,
                     const float* __restrict__ bq, const float* __restrict__ bk,
                     const float* __restrict__ bv)
{
    extern __shared__ char sm[];
    __half* smh = (__half*)sm;
    const int tid = threadIdx.x, wid = tid >> 5, lane = tid & 31;
    const int g = lane >> 2, tg = lane & 3;
    const int bth = bth0 + blockIdx.x;
    const int bt = bth >> 3, h = bth & 7;     // h fastest -> adjacent CTAs share X in L2
    const int wn = wid * 48;

    const uint32_t sb = smem_u32(sm);
    const __half* Xp = g_xh + (size_t)bt * 64 * 512;
    const __half* Wb = g_wqkv + (size_t)h * 64 * 512;

    // attn tiles alias the front of stage smem (guarded by the post-loop sync)
    __half* qs  = smh;
    __half* ks_ = qs + 4608;
    __half* vt  = ks_ + 4608;
    __half* ss  = vt + 4608;

    float acc[4][6][4];
    #pragma unroll
    for (int a = 0; a < 4; a++)
        #pragma unroll
        for (int b = 0; b < 6; b++)
            #pragma unroll
            for (int c = 0; c < 4; c++) acc[a][b][c] = 0.f;

    auto fill = [&](int s, int kt) {
        uint32_t As = sb + s * FSTG;
        uint32_t Bs = As + 8192;
        int koff = kt * 64;
        #pragma unroll
        for (int it = 0; it < 4; it++) {              // A: 64 rows x 128B
            int i = tid + it * 128;
            int r = i >> 3, c8 = i & 7;
            cp16(As + r * 128 + ((c8 ^ (r & 7)) << 4), Xp + (size_t)r * 512 + koff + c8 * 8);
        }
        #pragma unroll
        for (int it = 0; it < 12; it++) {             // B: 192 rows (3x64) x 128B
            int i = tid + it * 128;
            int r = i >> 3, c8 = i & 7;
            const __half* src = Wb + (size_t)(r >> 6) * (DD*DD) + (size_t)(r & 63) * 512 + koff + c8 * 8;
            cp16(Bs + r * 128 + ((c8 ^ (r & 7)) << 4), src);
        }
        cp_commit();
    };

    fill(0, 0);
    for (int kt = 0; kt < 8; kt++) {
        asm volatile("cp.async.wait_group 0;" ::: "memory");  // stage kt&1 data landed
        __syncthreads();   // all warps done with compute kt-1 (stage (kt+1)&1 now free)
        if (kt + 1 < 8) fill((kt + 1) & 1, kt + 1);

        char* As = sm + (kt & 1) * FSTG;
        char* Bs = As + 8192;

        #pragma unroll
        for (int ks = 0; ks < 4; ks++) {
            int c0 = ks * 2;
            int sel0 = (c0 ^ g) << 4, sel1 = ((c0 + 1) ^ g) << 4;
            uint32_t af[4][4], bf[6][2];
            #pragma unroll
            for (int im = 0; im < 4; im++) {
                int r = im * 16 + g;
                char* p0 = As + r * 128 + 4 * tg;
                char* p1 = As + (r + 8) * 128 + 4 * tg;
                af[im][0] = *(uint32_t*)(p0 + sel0);
                af[im][1] = *(uint32_t*)(p1 + sel0);
                af[im][2] = *(uint32_t*)(p0 + sel1);
                af[im][3] = *(uint32_t*)(p1 + sel1);
            }
            #pragma unroll
            for (int in = 0; in < 6; in++) {
                int n = wn + in * 8 + g;
                char* p = Bs + n * 128 + 4 * tg;
                bf[in][0] = *(uint32_t*)(p + sel0);
                bf[in][1] = *(uint32_t*)(p + sel1);
            }
            #pragma unroll
            for (int im = 0; im < 4; im++)
                #pragma unroll
                for (int in = 0; in < 6; in++)
                    mma_f16(acc[im][in], af[im][0], af[im][1], af[im][2], af[im][3],
                            bf[in][0], bf[in][1]);
        }
    }
    __syncthreads();   // all warps done reading stage smem before attn tiles alias it

    // epilogue: bias + fp16, route to qs / ks / vt(transposed)
    #pragma unroll
    for (int in = 0; in < 6; in++) {
        int col = wn + in * 8 + 2 * tg;       // even; col,col+1 same region
        int t = col >> 6, lc = col & 63;
        const float* bias = (t == 0) ? bq : (t == 1) ? bk : bv;
        float b0 = bias[h * 64 + lc], b1 = bias[h * 64 + lc + 1];
        #pragma unroll
        for (int im = 0; im < 4; im++) {
            int r0 = im * 16 + g, r1 = r0 + 8;
            __half h00 = __float2half_rn(acc[im][in][0] + b0);
            __half h01 = __float2half_rn(acc[im][in][1] + b1);
            __half h10 = __float2half_rn(acc[im][in][2] + b0);
            __half h11 = __float2half_rn(acc[im][in][3] + b1);
            if (t == 0) {
                __half2 v0; v0.x = h00; v0.y = h01;
                __half2 v1; v1.x = h10; v1.y = h11;
                *(__half2*)(qs + r0 * 72 + lc) = v0;
                *(__half2*)(qs + r1 * 72 + lc) = v1;
            } else if (t == 1) {
                __half2 v0; v0.x = h00; v0.y = h01;
                __half2 v1; v1.x = h10; v1.y = h11;
                *(__half2*)(ks_ + r0 * 72 + lc) = v0;
                *(__half2*)(ks_ + r1 * 72 + lc) = v1;
            } else {
                vt[lc * 72 + r0] = h00; vt[(lc + 1) * 72 + r0] = h01;
                vt[lc * 72 + r1] = h10; vt[(lc + 1) * 72 + r1] = h11;
            }
        }
    }
    __syncthreads();   // q/k/vt tiles complete across all warps

    // ------------- attention (R5 body) -------------
    const int mr = wid * 16;
    float c[8][4];
    #pragma unroll
    for (int in = 0; in < 8; in++)
        #pragma unroll
        for (int j = 0; j < 4; j++) c[in][j] = 0.f;

    // scores = q @ k^T
    #pragma unroll
    for (int ks4 = 0; ks4 < 4; ks4++) {
        int koff = ks4 * 16;
        uint32_t a0 = *(uint32_t*)(qs + (mr + g    ) * 72 + koff + 2 * tg);
        uint32_t a1 = *(uint32_t*)(qs + (mr + g + 8) * 72 + koff + 2 * tg);
        uint32_t a2 = *(uint32_t*)(qs + (mr + g    ) * 72 + koff + 2 * tg + 8);
        uint32_t a3 = *(uint32_t*)(qs + (mr + g + 8) * 72 + koff + 2 * tg + 8);
        #pragma unroll
        for (int in = 0; in < 8; in++) {
            int nr = in * 8 + g;
            uint32_t b0 = *(uint32_t*)(ks_ + nr * 72 + koff + 2 * tg);
            uint32_t b1 = *(uint32_t*)(ks_ + nr * 72 + koff + 2 * tg + 8);
            mma_f16(c[in], a0, a1, a2, a3, b0, b1);
        }
    }

    // softmax (scale 1/8)
    const float scale = 0.125f;
    float mx0 = -1e30f, mx1 = -1e30f;
    #pragma unroll
    for (int in = 0; in < 8; in++) {
        c[in][0] *= scale; c[in][1] *= scale;
        c[in][2] *= scale; c[in][3] *= scale;
        mx0 = fmaxf(mx0, fmaxf(c[in][0], c[in][1]));
        mx1 = fmaxf(mx1, fmaxf(c[in][2], c[in][3]));
    }
    mx0 = fmaxf(mx0, __shfl_xor_sync(0xffffffffu, mx0, 1));
    mx0 = fmaxf(mx0, __shfl_xor_sync(0xffffffffu, mx0, 2));
    mx1 = fmaxf(mx1, __shfl_xor_sync(0xffffffffu, mx1, 1));
    mx1 = fmaxf(mx1, __shfl_xor_sync(0xffffffffu, mx1, 2));

    float s0 = 0.f, s1 = 0.f;
    #pragma unroll
    for (int in = 0; in < 8; in++) {
        c[in][0] = __expf(c[in][0] - mx0); s0 += c[in][0];
        c[in][1] = __expf(c[in][1] - mx0); s0 += c[in][1];
        c[in][2] = __expf(c[in][2] - mx1); s1 += c[in][2];
        c[in][3] = __expf(c[in][3] - mx1); s1 += c[in][3];
    }
    s0 += __shfl_xor_sync(0xffffffffu, s0, 1);
    s0 += __shfl_xor_sync(0xffffffffu, s0, 2);
    s1 += __shfl_xor_sync(0xffffffffu, s1, 1);
    s1 += __shfl_xor_sync(0xffffffffu, s1, 2);
    float inv0 = 1.f / s0, inv1 = 1.f / s1;

    // write P (own warp rows)
    #pragma unroll
    for (int in = 0; in < 8; in++) {
        int col = in * 8 + 2 * tg;
        *(__half2*)(ss + (mr + g    ) * 72 + col) = __floats2half2_rn(c[in][0] * inv0, c[in][1] * inv0);
        *(__half2*)(ss + (mr + g + 8) * 72 + col) = __floats2half2_rn(c[in][2] * inv1, c[in][3] * inv1);
    }
    __syncwarp();

    #pragma unroll
    for (int in = 0; in < 8; in++)
        #pragma unroll
        for (int j = 0; j < 4; j++) c[in][j] = 0.f;

    // out = P @ V   (A = ss[m][m'] own rows, B[k=m'][n=dk] = vt[dk][m'])
    #pragma unroll
    for (int ks4 = 0; ks4 < 4; ks4++) {
        int koff = ks4 * 16;
        uint32_t a0 = *(uint32_t*)(ss + (mr + g    ) * 72 + koff + 2 * tg);
        uint32_t a1 = *(uint32_t*)(ss + (mr + g + 8) * 72 + koff + 2 * tg);
        uint32_t a2 = *(uint32_t*)(ss + (mr + g    ) * 72 + koff + 2 * tg + 8);
        uint32_t a3 = *(uint32_t*)(ss + (mr + g + 8) * 72 + koff + 2 * tg + 8);
        #pragma unroll
        for (int in = 0; in < 8; in++) {
            int nr = in * 8 + g;
            uint32_t b0 = *(uint32_t*)(vt + nr * 72 + koff + 2 * tg);
            uint32_t b1 = *(uint32_t*)(vt + nr * 72 + koff + 2 * tg + 8);
            mma_f16(c[in], a0, a1, a2, a3, b0, b1);
        }
    }

    // stage output tile into ss (own warp rows)
    #pragma unroll
    for (int in = 0; in < 8; in++) {
        int col = in * 8 + 2 * tg;
        *(__half2*)(ss + (mr + g    ) * 72 + col) = __floats2half2_rn(c[in][0], c[in][1]);
        *(__half2*)(ss + (mr + g + 8) * 72 + col) = __floats2half2_rn(c[in][2], c[in][3]);
    }
    __syncthreads();

    // coalesced store: 2 threads per row, 64B each -> full 128B segments
    {
        __half* dst = g_a + ((size_t)bt * 64) * 512 + h * 64;
        int row = tid >> 1, part = tid & 1;
        const uint4* sp = (const uint4*)(ss + row * 72 + part * 32);
        uint4* dp = (uint4*)(dst + (size_t)row * 512 + part * 32);
        dp[0] = sp[0]; dp[1] = sp[1]; dp[2] = sp[2]; dp[3] = sp[3];
    }
}

// ---------------------------------------------------------------------------
// Out-projection GEMM (R13-proven): D[128x128] of out = g_a @ Wo^T + bo
// 3-stage cp.async, BK=64, 4 warps of 64x64, 2 CTAs/SM, one sync per kt.
// ---------------------------------------------------------------------------
#define STG 32768
#define GEMM_SMEM (3*STG)

__device__ __forceinline__ void fill_stage(uint32_t smem_base, int s,
                                           const __half* __restrict__ Ap,
                                           const __half* __restrict__ Bp,
                                           int kt, int tid)
{
    uint32_t As = smem_base + s * STG;
    uint32_t Bs = As + 16384;
    int koff = kt * 64;
    #pragma unroll
    for (int it = 0; it < 8; it++) {
        int i = tid + it * 128;
        int r = i >> 3, c8 = i & 7;
        cp16(As + r * 128 + ((c8 ^ (r & 7)) << 4), Ap + (size_t)r * 512 + koff + c8 * 8);
    }
    #pragma unroll
    for (int it = 0; it < 8; it++) {
        int i = tid + it * 128;
        int r = i >> 3, c8 = i & 7;
        cp16(Bs + r * 128 + ((c8 ^ (r & 7)) << 4), Bp + (size_t)r * 512 + koff + c8 * 8);
    }
    cp_commit();
}

__global__ __launch_bounds__(128, 2)
void gemm_out(const __half* __restrict__ A, const __half* __restrict__ Bw,
              const float* __restrict__ bias, float* __restrict__ out)
{
    extern __shared__ char sm[];
    const int tid = threadIdx.x, wid = tid >> 5, lane = tid & 31;
    const int g = lane >> 2, tg = lane & 3;
    const int n0 = blockIdx.x * 128, m0 = blockIdx.y * 128;
    const int wm = (wid & 1) * 64, wn = (wid >> 1) * 64;

    uint32_t sbase = smem_u32(sm);
    const __half* Ap = A + (size_t)m0 * 512;
    const __half* Bp = Bw + (size_t)n0 * 512;

    float acc[4][8][4];
    #pragma unroll
    for (int a = 0; a < 4; a++)
        #pragma unroll
        for (int b = 0; b < 8; b++)
            #pragma unroll
            for (int c = 0; c < 4; c++) acc[a][b][c] = 0.f;

    fill_stage(sbase, 0, Ap, Bp, 0, tid);
    fill_stage(sbase, 1, Ap, Bp, 1, tid);

    for (int kt = 0; kt < 8; kt++) {
        if (kt < 7) asm volatile("cp.async.wait_group 1;" ::: "memory");
        else        asm volatile("cp.async.wait_group 0;" ::: "memory");
        __syncthreads();
        if (kt + 2 < 8) fill_stage(sbase, (kt + 2) % 3, Ap, Bp, kt + 2, tid);

        char* As = sm + (kt % 3) * STG;
        char* Bs = As + 16384;

        #pragma unroll
        for (int ks = 0; ks < 4; ks++) {
            int c0 = ks * 2;
            int sel0 = (c0 ^ g) << 4, sel1 = ((c0 + 1) ^ g) << 4;
            uint32_t af[4][4], bf[8][2];
            #pragma unroll
            for (int im = 0; im < 4; im++) {
                int r = wm + im * 16 + g;
                char* p0 = As + r * 128 + 4 * tg;
                char* p1 = As + (r + 8) * 128 + 4 * tg;
                af[im][0] = *(uint32_t*)(p0 + sel0);
                af[im][1] = *(uint32_t*)(p1 + sel0);
                af[im][2] = *(uint32_t*)(p0 + sel1);
                af[im][3] = *(uint32_t*)(p1 + sel1);
            }
            #pragma unroll
            for (int in = 0; in < 8; in++) {
                int n = wn + in * 8 + g;
                char* p = Bs + n * 128 + 4 * tg;
                bf[in][0] = *(uint32_t*)(p + sel0);
                bf[in][1] = *(uint32_t*)(p + sel1);
            }
            #pragma unroll
            for (int im = 0; im < 4; im++)
                #pragma unroll
                for (int in = 0; in < 8; in++)
                    mma_f16(acc[im][in], af[im][0], af[im][1], af[im][2], af[im][3],
                            bf[in][0], bf[in][1]);
        }
    }

    #pragma unroll
    for (int im = 0; im < 4; im++) {
        #pragma unroll
        for (int in = 0; in < 8; in++) {
            int col = n0 + wn + in * 8 + 2 * tg;
            float bb0 = bias[col], bb1 = bias[col + 1];
            int r0 = m0 + wm + im * 16 + g;
            float2 v0 = {acc[im][in][0] + bb0, acc[im][in][1] + bb1};
            float2 v1 = {acc[im][in][2] + bb0, acc[im][in][3] + bb1};
            *(float2*)(out + (size_t)r0 * 512 + col) = v0;
            *(float2*)(out + (size_t)(r0 + 8) * 512 + col) = v1;
        }
    }
}

// ---------------------------------------------------------------------------
extern "C" void kernel_launch(void* const* d_in, const int* in_sizes, int n_in,
                              void* d_out, int out_size)
{
    const float* x  = (const float*)d_in[0];
    const float* Wq = (const float*)d_in[1];
    const float* bq = (const float*)d_in[2];
    const float* Wk = (const float*)d_in[3];
    const float* bk = (const float*)d_in[4];
    const float* Wv = (const float*)d_in[5];
    const float* bv = (const float*)d_in[6];
    const float* Wo = (const float*)d_in[7];
    const float* bo = (const float*)d_in[8];
    float* out = (float*)d_out;

    void *pxh, *pwqkv, *pwo, *pa;
    cudaGetSymbolAddress(&pxh,   g_xh);
    cudaGetSymbolAddress(&pwqkv, g_wqkv);
    cudaGetSymbolAddress(&pwo,   g_wo);
    cudaGetSymbolAddress(&pa,    g_a);

    cudaFuncSetAttribute(qkv_attn_kernel, cudaFuncAttributeMaxDynamicSharedMemorySize, FUSED_SMEM);
    cudaFuncSetAttribute(gemm_out, cudaFuncAttributeMaxDynamicSharedMemorySize, GEMM_SMEM);

    // Fork-join side stream + events (created fresh each call; kernel_launch is
    // invoked only twice — correctness + capture — so no resource growth).
    cudaStream_t s2;
    cudaStreamCreateWithFlags(&s2, cudaStreamNonBlocking);
    cudaEvent_t evA, evB;
    cudaEventCreateWithFlags(&evA, cudaEventDisableTiming);
    cudaEventCreateWithFlags(&evB, cudaEventDisableTiming);

    const int N4   = NROWS * DD / 4;       // total float4s in X
    const int N4LO = N4 / 4;               // first 1/4 (bt 0..511)
    const int N4HI = N4 - N4LO;            // remaining 3/4

    // 1) weights + first 1/4 of X on the main stream
    conv_w<<<(4*DD*DD/4 + 255)/256, 256>>>((const float4*)Wq, (const float4*)Wk,
                                           (const float4*)Wv, (const float4*)Wo,
                                           (uint2*)pwqkv, (uint2*)pwo);
    conv_h<<<(N4LO + 255)/256, 256>>>((const float4*)x, (uint2*)pxh, N4LO);
    cudaEventRecord(evA, 0);

    // side stream: remaining 3/4 of X, overlapped with fused chunk 1
    cudaStreamWaitEvent(s2, evA, 0);
    conv_h<<<(N4HI + 255)/256, 256, 0, s2>>>((const float4*)x + N4LO,
                                             (uint2*)pxh + N4LO, N4HI);
    cudaEventRecord(evB, s2);

    // 2) fused chunk 1: bth 0..4095 (bt 0..511) — only needs the first 1/4 of X
    qkv_attn_kernel<<<NBTH/4, 128, FUSED_SMEM>>>(0, bq, bk, bv);

    // join: remaining fused work needs the rest of X
    cudaStreamWaitEvent(0, evB, 0);
    qkv_attn_kernel<<<NBTH - NBTH/4, 128, FUSED_SMEM>>>(NBTH/4, bq, bk, bv);

    // 3) output projection: out = g_a @ Wo^T + bo
    dim3 go(4, NROWS / 128);
    gemm_out<<<go, 128, GEMM_SMEM>>>((const __half*)pa, (const __half*)pwo, bo, out);
}

// round 15
// speedup vs baseline: 1.0146x; 1.0146x over previous
#include <cuda_runtime.h>
#include <cuda_fp16.h>
#include <cstdint>

// Problem constants
#define BB 8
#define TT 256
#define MM 64
#define DD 512
#define HH 8
#define DKK 64
#define NROWS (BB*TT*MM)        // 131072
#define NBTH  (BB*TT*HH)        // 16384

// Scratch (device globals: allocation-free)
__device__ __half g_xh[(size_t)NROWS*DD];      // X in fp16
__device__ __half g_wqkv[3*DD*DD];             // packed Wq|Wk|Wv fp16 (rows = features)
__device__ __half g_wo[DD*DD];                 // Wo fp16
__device__ __half g_a[(size_t)NROWS*DD];       // (btm, d) fp16 attention output

__device__ __forceinline__ uint32_t smem_u32(const void* p) {
    uint32_t a;
    asm("{ .reg .u64 t; cvta.to.shared.u64 t, %1; cvt.u32.u64 %0, t; }" : "=r"(a) : "l"(p));
    return a;
}
__device__ __forceinline__ void cp16(uint32_t saddr, const void* gaddr) {
    asm volatile("cp.async.cg.shared.global [%0], [%1], 16;" :: "r"(saddr), "l"(gaddr) : "memory");
}
__device__ __forceinline__ void cp_commit() {
    asm volatile("cp.async.commit_group;" ::: "memory");
}

__device__ __forceinline__ void mma_f16(float* c,
    uint32_t a0, uint32_t a1, uint32_t a2, uint32_t a3, uint32_t b0, uint32_t b1)
{
    asm volatile(
        "mma.sync.aligned.m16n8k16.row.col.f32.f16.f16.f32 "
        "{%0,%1,%2,%3}, {%4,%5,%6,%7}, {%8,%9}, {%0,%1,%2,%3};"
        : "+f"(c[0]), "+f"(c[1]), "+f"(c[2]), "+f"(c[3])
        : "r"(a0), "r"(a1), "r"(a2), "r"(a3), "r"(b0), "r"(b1));
}

// ---------------------------------------------------------------------------
// conv kernels: fp32 -> fp16
// ---------------------------------------------------------------------------
__device__ __forceinline__ uint2 cvt4(float4 v) {
    __half2 h0 = __floats2half2_rn(v.x, v.y);
    __half2 h1 = __floats2half2_rn(v.z, v.w);
    uint2 r;
    r.x = *(uint32_t*)&h0;
    r.y = *(uint32_t*)&h1;
    return r;
}

// X conversion: 2 float4s in (32B), one uint4 out (16B) per thread.
__global__ void conv_h(const float4* __restrict__ in, uint4* __restrict__ out, int n8)
{
    int i = blockIdx.x * blockDim.x + threadIdx.x;
    if (i >= n8) return;
    uint2 a = cvt4(in[2 * i]);
    uint2 b = cvt4(in[2 * i + 1]);
    uint4 r;
    r.x = a.x; r.y = a.y; r.z = b.x; r.w = b.y;
    out[i] = r;
}

__global__ void conv_w(const float4* __restrict__ wq, const float4* __restrict__ wk,
                       const float4* __restrict__ wv, const float4* __restrict__ wo,
                       uint2* __restrict__ oqkv, uint2* __restrict__ oo)
{
    int i = blockIdx.x * blockDim.x + threadIdx.x;   // 0 .. 4*65536-1
    int t = i >> 16, j = i & 65535;
    const float4* src = (t == 0) ? wq : (t == 1) ? wk : (t == 2) ? wv : wo;
    uint2* dst = (t == 3) ? oo : (oqkv + (size_t)t * (DD*DD/4));
    dst[j] = cvt4(src[j]);
}

// ---------------------------------------------------------------------------
// Fused QKV + attention kernel (R13-proven).
// One CTA per (bt, h), 128 threads, 3 CTAs/SM.
//
// Phase 1 (GEMM): Y[64 x 192] = X[bt rows, 512] @ [Wq_h | Wk_h | Wv_h]^T
//   2-stage cp.async, fill-AFTER-sync -> one __syncthreads per kt.
//   Warp tile 64x48. Epilogue adds bias -> fp16 smem tiles:
//     cols 0-63 -> qs[m][dk], 64-127 -> ks[m'][dk], 128-191 -> vt[dk][m'].
// Phase 2 (attention, R5-proven body) -> coalesced store to g_a.
//
// smem: 2 stages x 32768 B = 65536. Attn tiles (qs/ks/vt/ss, 36864 B)
// ALIAS bytes [0, 36864) of stage smem; a post-loop __syncthreads orders the
// last compute reads before the epilogue writes.
// ---------------------------------------------------------------------------
#define FSTG 32768
#define FUSED_SMEM (2*FSTG)

__global__ __launch_bounds__(128, 3)
void qkv_attn_kernel(const float* __restrict__ bq, const float* __restrict__ bk,
                     const float* __restrict__ bv)
{
    extern __shared__ char sm[];
    __half* smh = (__half*)sm;
    const int tid = threadIdx.x, wid = tid >> 5, lane = tid & 31;
    const int g = lane >> 2, tg = lane & 3;
    const int bth = blockIdx.x;
    const int bt = bth >> 3, h = bth & 7;     // h fastest -> adjacent CTAs share X in L2
    const int wn = wid * 48;

    const uint32_t sb = smem_u32(sm);
    const __half* Xp = g_xh + (size_t)bt * 64 * 512;
    const __half* Wb = g_wqkv + (size_t)h * 64 * 512;

    // attn tiles alias the front of stage smem (guarded by the post-loop sync)
    __half* qs  = smh;
    __half* ks_ = qs + 4608;
    __half* vt  = ks_ + 4608;
    __half* ss  = vt + 4608;

    float acc[4][6][4];
    #pragma unroll
    for (int a = 0; a < 4; a++)
        #pragma unroll
        for (int b = 0; b < 6; b++)
            #pragma unroll
            for (int c = 0; c < 4; c++) acc[a][b][c] = 0.f;

    auto fill = [&](int s, int kt) {
        uint32_t As = sb + s * FSTG;
        uint32_t Bs = As + 8192;
        int koff = kt * 64;
        #pragma unroll
        for (int it = 0; it < 4; it++) {              // A: 64 rows x 128B
            int i = tid + it * 128;
            int r = i >> 3, c8 = i & 7;
            cp16(As + r * 128 + ((c8 ^ (r & 7)) << 4), Xp + (size_t)r * 512 + koff + c8 * 8);
        }
        #pragma unroll
        for (int it = 0; it < 12; it++) {             // B: 192 rows (3x64) x 128B
            int i = tid + it * 128;
            int r = i >> 3, c8 = i & 7;
            const __half* src = Wb + (size_t)(r >> 6) * (DD*DD) + (size_t)(r & 63) * 512 + koff + c8 * 8;
            cp16(Bs + r * 128 + ((c8 ^ (r & 7)) << 4), src);
        }
        cp_commit();
    };

    fill(0, 0);
    for (int kt = 0; kt < 8; kt++) {
        asm volatile("cp.async.wait_group 0;" ::: "memory");  // stage kt&1 data landed
        __syncthreads();   // all warps done with compute kt-1 (stage (kt+1)&1 now free)
        if (kt + 1 < 8) fill((kt + 1) & 1, kt + 1);

        char* As = sm + (kt & 1) * FSTG;
        char* Bs = As + 8192;

        #pragma unroll
        for (int ks = 0; ks < 4; ks++) {
            int c0 = ks * 2;
            int sel0 = (c0 ^ g) << 4, sel1 = ((c0 + 1) ^ g) << 4;
            uint32_t af[4][4], bf[6][2];
            #pragma unroll
            for (int im = 0; im < 4; im++) {
                int r = im * 16 + g;
                char* p0 = As + r * 128 + 4 * tg;
                char* p1 = As + (r + 8) * 128 + 4 * tg;
                af[im][0] = *(uint32_t*)(p0 + sel0);
                af[im][1] = *(uint32_t*)(p1 + sel0);
                af[im][2] = *(uint32_t*)(p0 + sel1);
                af[im][3] = *(uint32_t*)(p1 + sel1);
            }
            #pragma unroll
            for (int in = 0; in < 6; in++) {
                int n = wn + in * 8 + g;
                char* p = Bs + n * 128 + 4 * tg;
                bf[in][0] = *(uint32_t*)(p + sel0);
                bf[in][1] = *(uint32_t*)(p + sel1);
            }
            #pragma unroll
            for (int im = 0; im < 4; im++)
                #pragma unroll
                for (int in = 0; in < 6; in++)
                    mma_f16(acc[im][in], af[im][0], af[im][1], af[im][2], af[im][3],
                            bf[in][0], bf[in][1]);
        }
    }
    __syncthreads();   // all warps done reading stage smem before attn tiles alias it

    // epilogue: bias + fp16, route to qs / ks / vt(transposed)
    #pragma unroll
    for (int in = 0; in < 6; in++) {
        int col = wn + in * 8 + 2 * tg;       // even; col,col+1 same region
        int t = col >> 6, lc = col & 63;
        const float* bias = (t == 0) ? bq : (t == 1) ? bk : bv;
        float b0 = bias[h * 64 + lc], b1 = bias[h * 64 + lc + 1];
        #pragma unroll
        for (int im = 0; im < 4; im++) {
            int r0 = im * 16 + g, r1 = r0 + 8;
            __half h00 = __float2half_rn(acc[im][in][0] + b0);
            __half h01 = __float2half_rn(acc[im][in][1] + b1);
            __half h10 = __float2half_rn(acc[im][in][2] + b0);
            __half h11 = __float2half_rn(acc[im][in][3] + b1);
            if (t == 0) {
                __half2 v0; v0.x = h00; v0.y = h01;
                __half2 v1; v1.x = h10; v1.y = h11;
                *(__half2*)(qs + r0 * 72 + lc) = v0;
                *(__half2*)(qs + r1 * 72 + lc) = v1;
            } else if (t == 1) {
                __half2 v0; v0.x = h00; v0.y = h01;
                __half2 v1; v1.x = h10; v1.y = h11;
                *(__half2*)(ks_ + r0 * 72 + lc) = v0;
                *(__half2*)(ks_ + r1 * 72 + lc) = v1;
            } else {
                vt[lc * 72 + r0] = h00; vt[(lc + 1) * 72 + r0] = h01;
                vt[lc * 72 + r1] = h10; vt[(lc + 1) * 72 + r1] = h11;
            }
        }
    }
    __syncthreads();   // q/k/vt tiles complete across all warps

    // ------------- attention (R5 body) -------------
    const int mr = wid * 16;
    float c[8][4];
    #pragma unroll
    for (int in = 0; in < 8; in++)
        #pragma unroll
        for (int j = 0; j < 4; j++) c[in][j] = 0.f;

    // scores = q @ k^T
    #pragma unroll
    for (int ks4 = 0; ks4 < 4; ks4++) {
        int koff = ks4 * 16;
        uint32_t a0 = *(uint32_t*)(qs + (mr + g    ) * 72 + koff + 2 * tg);
        uint32_t a1 = *(uint32_t*)(qs + (mr + g + 8) * 72 + koff + 2 * tg);
        uint32_t a2 = *(uint32_t*)(qs + (mr + g    ) * 72 + koff + 2 * tg + 8);
        uint32_t a3 = *(uint32_t*)(qs + (mr + g + 8) * 72 + koff + 2 * tg + 8);
        #pragma unroll
        for (int in = 0; in < 8; in++) {
            int nr = in * 8 + g;
            uint32_t b0 = *(uint32_t*)(ks_ + nr * 72 + koff + 2 * tg);
            uint32_t b1 = *(uint32_t*)(ks_ + nr * 72 + koff + 2 * tg + 8);
            mma_f16(c[in], a0, a1, a2, a3, b0, b1);
        }
    }

    // softmax (scale 1/8)
    const float scale = 0.125f;
    float mx0 = -1e30f, mx1 = -1e30f;
    #pragma unroll
    for (int in = 0; in < 8; in++) {
        c[in][0] *= scale; c[in][1] *= scale;
        c[in][2] *= scale; c[in][3] *= scale;
        mx0 = fmaxf(mx0, fmaxf(c[in][0], c[in][1]));
        mx1 = fmaxf(mx1, fmaxf(c[in][2], c[in][3]));
    }
    mx0 = fmaxf(mx0, __shfl_xor_sync(0xffffffffu, mx0, 1));
    mx0 = fmaxf(mx0, __shfl_xor_sync(0xffffffffu, mx0, 2));
    mx1 = fmaxf(mx1, __shfl_xor_sync(0xffffffffu, mx1, 1));
    mx1 = fmaxf(mx1, __shfl_xor_sync(0xffffffffu, mx1, 2));

    float s0 = 0.f, s1 = 0.f;
    #pragma unroll
    for (int in = 0; in < 8; in++) {
        c[in][0] = __expf(c[in][0] - mx0); s0 += c[in][0];
        c[in][1] = __expf(c[in][1] - mx0); s0 += c[in][1];
        c[in][2] = __expf(c[in][2] - mx1); s1 += c[in][2];
        c[in][3] = __expf(c[in][3] - mx1); s1 += c[in][3];
    }
    s0 += __shfl_xor_sync(0xffffffffu, s0, 1);
    s0 += __shfl_xor_sync(0xffffffffu, s0, 2);
    s1 += __shfl_xor_sync(0xffffffffu, s1, 1);
    s1 += __shfl_xor_sync(0xffffffffu, s1, 2);
    float inv0 = 1.f / s0, inv1 = 1.f / s1;

    // write P (own warp rows)
    #pragma unroll
    for (int in = 0; in < 8; in++) {
        int col = in * 8 + 2 * tg;
        *(__half2*)(ss + (mr + g    ) * 72 + col) = __floats2half2_rn(c[in][0] * inv0, c[in][1] * inv0);
        *(__half2*)(ss + (mr + g + 8) * 72 + col) = __floats2half2_rn(c[in][2] * inv1, c[in][3] * inv1);
    }
    __syncwarp();

    #pragma unroll
    for (int in = 0; in < 8; in++)
        #pragma unroll
        for (int j = 0; j < 4; j++) c[in][j] = 0.f;

    // out = P @ V   (A = ss[m][m'] own rows, B[k=m'][n=dk] = vt[dk][m'])
    #pragma unroll
    for (int ks4 = 0; ks4 < 4; ks4++) {
        int koff = ks4 * 16;
        uint32_t a0 = *(uint32_t*)(ss + (mr + g    ) * 72 + koff + 2 * tg);
        uint32_t a1 = *(uint32_t*)(ss + (mr + g + 8) * 72 + koff + 2 * tg);
        uint32_t a2 = *(uint32_t*)(ss + (mr + g    ) * 72 + koff + 2 * tg + 8);
        uint32_t a3 = *(uint32_t*)(ss + (mr + g + 8) * 72 + koff + 2 * tg + 8);
        #pragma unroll
        for (int in = 0; in < 8; in++) {
            int nr = in * 8 + g;
            uint32_t b0 = *(uint32_t*)(vt + nr * 72 + koff + 2 * tg);
            uint32_t b1 = *(uint32_t*)(vt + nr * 72 + koff + 2 * tg + 8);
            mma_f16(c[in], a0, a1, a2, a3, b0, b1);
        }
    }

    // stage output tile into ss (own warp rows)
    #pragma unroll
    for (int in = 0; in < 8; in++) {
        int col = in * 8 + 2 * tg;
        *(__half2*)(ss + (mr + g    ) * 72 + col) = __floats2half2_rn(c[in][0], c[in][1]);
        *(__half2*)(ss + (mr + g + 8) * 72 + col) = __floats2half2_rn(c[in][2], c[in][3]);
    }
    __syncthreads();

    // coalesced store: 2 threads per row, 64B each -> full 128B segments
    {
        __half* dst = g_a + ((size_t)bt * 64) * 512 + h * 64;
        int row = tid >> 1, part = tid & 1;
        const uint4* sp = (const uint4*)(ss + row * 72 + part * 32);
        uint4* dp = (uint4*)(dst + (size_t)row * 512 + part * 32);
        dp[0] = sp[0]; dp[1] = sp[1]; dp[2] = sp[2]; dp[3] = sp[3];
    }
}

// ---------------------------------------------------------------------------
// Out-projection GEMM (R13-proven): D[128x128] of out = g_a @ Wo^T + bo
// 3-stage cp.async, BK=64, 4 warps of 64x64, 2 CTAs/SM, one sync per kt.
// ---------------------------------------------------------------------------
#define STG 32768
#define GEMM_SMEM (3*STG)

__device__ __forceinline__ void fill_stage(uint32_t smem_base, int s,
                                           const __half* __restrict__ Ap,
                                           const __half* __restrict__ Bp,
                                           int kt, int tid)
{
    uint32_t As = smem_base + s * STG;
    uint32_t Bs = As + 16384;
    int koff = kt * 64;
    #pragma unroll
    for (int it = 0; it < 8; it++) {
        int i = tid + it * 128;
        int r = i >> 3, c8 = i & 7;
        cp16(As + r * 128 + ((c8 ^ (r & 7)) << 4), Ap + (size_t)r * 512 + koff + c8 * 8);
    }
    #pragma unroll
    for (int it = 0; it < 8; it++) {
        int i = tid + it * 128;
        int r = i >> 3, c8 = i & 7;
        cp16(Bs + r * 128 + ((c8 ^ (r & 7)) << 4), Bp + (size_t)r * 512 + koff + c8 * 8);
    }
    cp_commit();
}

__global__ __launch_bounds__(128, 2)
void gemm_out(const __half* __restrict__ A, const __half* __restrict__ Bw,
              const float* __restrict__ bias, float* __restrict__ out)
{
    extern __shared__ char sm[];
    const int tid = threadIdx.x, wid = tid >> 5, lane = tid & 31;
    const int g = lane >> 2, tg = lane & 3;
    const int n0 = blockIdx.x * 128, m0 = blockIdx.y * 128;
    const int wm = (wid & 1) * 64, wn = (wid >> 1) * 64;

    uint32_t sbase = smem_u32(sm);
    const __half* Ap = A + (size_t)m0 * 512;
    const __half* Bp = Bw + (size_t)n0 * 512;

    float acc[4][8][4];
    #pragma unroll
    for (int a = 0; a < 4; a++)
        #pragma unroll
        for (int b = 0; b < 8; b++)
            #pragma unroll
            for (int c = 0; c < 4; c++) acc[a][b][c] = 0.f;

    fill_stage(sbase, 0, Ap, Bp, 0, tid);
    fill_stage(sbase, 1, Ap, Bp, 1, tid);

    for (int kt = 0; kt < 8; kt++) {
        if (kt < 7) asm volatile("cp.async.wait_group 1;" ::: "memory");
        else        asm volatile("cp.async.wait_group 0;" ::: "memory");
        __syncthreads();
        if (kt + 2 < 8) fill_stage(sbase, (kt + 2) % 3, Ap, Bp, kt + 2, tid);

        char* As = sm + (kt % 3) * STG;
        char* Bs = As + 16384;

        #pragma unroll
        for (int ks = 0; ks < 4; ks++) {
            int c0 = ks * 2;
            int sel0 = (c0 ^ g) << 4, sel1 = ((c0 + 1) ^ g) << 4;
            uint32_t af[4][4], bf[8][2];
            #pragma unroll
            for (int im = 0; im < 4; im++) {
                int r = wm + im * 16 + g;
                char* p0 = As + r * 128 + 4 * tg;
                char* p1 = As + (r + 8) * 128 + 4 * tg;
                af[im][0] = *(uint32_t*)(p0 + sel0);
                af[im][1] = *(uint32_t*)(p1 + sel0);
                af[im][2] = *(uint32_t*)(p0 + sel1);
                af[im][3] = *(uint32_t*)(p1 + sel1);
            }
            #pragma unroll
            for (int in = 0; in < 8; in++) {
                int n = wn + in * 8 + g;
                char* p = Bs + n * 128 + 4 * tg;
                bf[in][0] = *(uint32_t*)(p + sel0);
                bf[in][1] = *(uint32_t*)(p + sel1);
            }
            #pragma unroll
            for (int im = 0; im < 4; im++)
                #pragma unroll
                for (int in = 0; in < 8; in++)
                    mma_f16(acc[im][in], af[im][0], af[im][1], af[im][2], af[im][3],
                            bf[in][0], bf[in][1]);
        }
    }

    #pragma unroll
    for (int im = 0; im < 4; im++) {
        #pragma unroll
        for (int in = 0; in < 8; in++) {
            int col = n0 + wn + in * 8 + 2 * tg;
            float bb0 = bias[col], bb1 = bias[col + 1];
            int r0 = m0 + wm + im * 16 + g;
            float2 v0 = {acc[im][in][0] + bb0, acc[im][in][1] + bb1};
            float2 v1 = {acc[im][in][2] + bb0, acc[im][in][3] + bb1};
            *(float2*)(out + (size_t)r0 * 512 + col) = v0;
            *(float2*)(out + (size_t)(r0 + 8) * 512 + col) = v1;
        }
    }
}

// ---------------------------------------------------------------------------
extern "C" void kernel_launch(void* const* d_in, const int* in_sizes, int n_in,
                              void* d_out, int out_size)
{
    const float* x  = (const float*)d_in[0];
    const float* Wq = (const float*)d_in[1];
    const float* bq = (const float*)d_in[2];
    const float* Wk = (const float*)d_in[3];
    const float* bk = (const float*)d_in[4];
    const float* Wv = (const float*)d_in[5];
    const float* bv = (const float*)d_in[6];
    const float* Wo = (const float*)d_in[7];
    const float* bo = (const float*)d_in[8];
    float* out = (float*)d_out;

    void *pxh, *pwqkv, *pwo, *pa;
    cudaGetSymbolAddress(&pxh,   g_xh);
    cudaGetSymbolAddress(&pwqkv, g_wqkv);
    cudaGetSymbolAddress(&pwo,   g_wo);
    cudaGetSymbolAddress(&pa,    g_a);

    // 1) fp32 -> fp16 conversions (X: 32B-in/16B-out per thread)
    const int N8 = NROWS * DD / 8;
    conv_h<<<(N8 + 255)/256, 256>>>((const float4*)x, (uint4*)pxh, N8);
    conv_w<<<(4*DD*DD/4 + 255)/256, 256>>>((const float4*)Wq, (const float4*)Wk,
                                           (const float4*)Wv, (const float4*)Wo,
                                           (uint2*)pwqkv, (uint2*)pwo);

    cudaFuncSetAttribute(qkv_attn_kernel, cudaFuncAttributeMaxDynamicSharedMemorySize, FUSED_SMEM);
    cudaFuncSetAttribute(gemm_out, cudaFuncAttributeMaxDynamicSharedMemorySize, GEMM_SMEM);

    // 2) fused QKV projection + attention: one CTA per (bt, h)
    qkv_attn_kernel<<<NBTH, 128, FUSED_SMEM>>>(bq, bk, bv);

    // 3) output projection: out = g_a @ Wo^T + bo
    dim3 go(4, NROWS / 128);
    gemm_out<<<go, 128, GEMM_SMEM>>>((const __half*)pa, (const __half*)pwo, bo, out);
}

// round 16
// speedup vs baseline: 1.0172x; 1.0026x over previous
#include <cuda_runtime.h>
#include <cuda_fp16.h>
#include <cstdint>

// Problem constants
#define BB 8
#define TT 256
#define MM 64
#define DD 512
#define HH 8
#define DKK 64
#define NROWS (BB*TT*MM)        // 131072
#define NBTH  (BB*TT*HH)        // 16384

// Scratch (device globals: allocation-free)
__device__ __half g_xh[(size_t)NROWS*DD];      // X in fp16
__device__ __half g_wqkv[3*DD*DD];             // packed Wq|Wk|Wv fp16 (rows = features)
__device__ __half g_wo[DD*DD];                 // Wo fp16
__device__ __half g_a[(size_t)NROWS*DD];       // (btm, d) fp16 attention output

__device__ __forceinline__ uint32_t smem_u32(const void* p) {
    uint32_t a;
    asm("{ .reg .u64 t; cvta.to.shared.u64 t, %1; cvt.u32.u64 %0, t; }" : "=r"(a) : "l"(p));
    return a;
}
__device__ __forceinline__ void cp16(uint32_t saddr, const void* gaddr) {
    asm volatile("cp.async.cg.shared.global [%0], [%1], 16;" :: "r"(saddr), "l"(gaddr) : "memory");
}
__device__ __forceinline__ void cp_commit() {
    asm volatile("cp.async.commit_group;" ::: "memory");
}

__device__ __forceinline__ void mma_f16(float* c,
    uint32_t a0, uint32_t a1, uint32_t a2, uint32_t a3, uint32_t b0, uint32_t b1)
{
    asm volatile(
        "mma.sync.aligned.m16n8k16.row.col.f32.f16.f16.f32 "
        "{%0,%1,%2,%3}, {%4,%5,%6,%7}, {%8,%9}, {%0,%1,%2,%3};"
        : "+f"(c[0]), "+f"(c[1]), "+f"(c[2]), "+f"(c[3])
        : "r"(a0), "r"(a1), "r"(a2), "r"(a3), "r"(b0), "r"(b1));
}

// ---------------------------------------------------------------------------
// Merged conversion kernel: fp32 -> fp16 for X and all four weight matrices
// in a single launch. Blocks [0, XBLK) convert X (32B in / 16B out per
// thread); blocks [XBLK, XBLK+WBLK) convert the weights (also widened).
// ---------------------------------------------------------------------------
__device__ __forceinline__ uint2 cvt4(float4 v) {
    __half2 h0 = __floats2half2_rn(v.x, v.y);
    __half2 h1 = __floats2half2_rn(v.z, v.w);
    uint2 r;
    r.x = *(uint32_t*)&h0;
    r.y = *(uint32_t*)&h1;
    return r;
}
__device__ __forceinline__ uint4 cvt8(const float4* p) {
    uint2 a = cvt4(p[0]);
    uint2 b = cvt4(p[1]);
    uint4 r;
    r.x = a.x; r.y = a.y; r.z = b.x; r.w = b.y;
    return r;
}

#define X_N8   (NROWS*DD/8)            // 8388608 uint4 outputs for X
#define XBLK   (X_N8/256)              // 32768 blocks
#define W_N8   (DD*DD/8)               // 32768 uint4 outputs per weight matrix
#define WBLK   (4*W_N8/256)            // 512 blocks

__global__ void conv_all(const float4* __restrict__ x, uint4* __restrict__ xh,
                         const float4* __restrict__ wq, const float4* __restrict__ wk,
                         const float4* __restrict__ wv, const float4* __restrict__ wo,
                         uint4* __restrict__ oqkv, uint4* __restrict__ oo)
{
    int b = blockIdx.x;
    if (b < XBLK) {
        int i = b * 256 + threadIdx.x;          // uint4 index into X output
        xh[i] = cvt8(x + 2 * (size_t)i);
    } else {
        int i = (b - XBLK) * 256 + threadIdx.x; // 0 .. 4*W_N8-1
        int t = i / W_N8, j = i % W_N8;
        const float4* src = (t == 0) ? wq : (t == 1) ? wk : (t == 2) ? wv : wo;
        uint4* dst = (t == 3) ? oo : (oqkv + (size_t)t * W_N8);
        dst[j] = cvt8(src + 2 * (size_t)j);
    }
}

// ---------------------------------------------------------------------------
// Fused QKV + attention kernel (R13/R15-proven).
// One CTA per (bt, h), 128 threads, 3 CTAs/SM.
//
// Phase 1 (GEMM): Y[64 x 192] = X[bt rows, 512] @ [Wq_h | Wk_h | Wv_h]^T
//   2-stage cp.async, fill-AFTER-sync -> one __syncthreads per kt.
//   Warp tile 64x48. Epilogue adds bias -> fp16 smem tiles:
//     cols 0-63 -> qs[m][dk], 64-127 -> ks[m'][dk], 128-191 -> vt[dk][m'].
// Phase 2 (attention, R5-proven body) -> coalesced store to g_a.
//
// smem: 2 stages x 32768 B = 65536. Attn tiles (qs/ks/vt/ss, 36864 B)
// ALIAS bytes [0, 36864) of stage smem; a post-loop __syncthreads orders the
// last compute reads before the epilogue writes.
// ---------------------------------------------------------------------------
#define FSTG 32768
#define FUSED_SMEM (2*FSTG)

__global__ __launch_bounds__(128, 3)
void qkv_attn_kernel(const float* __restrict__ bq, const float* __restrict__ bk,
                     const float* __restrict__ bv)
{
    extern __shared__ char sm[];
    __half* smh = (__half*)sm;
    const int tid = threadIdx.x, wid = tid >> 5, lane = tid & 31;
    const int g = lane >> 2, tg = lane & 3;
    const int bth = blockIdx.x;
    const int bt = bth >> 3, h = bth & 7;     // h fastest -> adjacent CTAs share X in L2
    const int wn = wid * 48;

    const uint32_t sb = smem_u32(sm);
    const __half* Xp = g_xh + (size_t)bt * 64 * 512;
    const __half* Wb = g_wqkv + (size_t)h * 64 * 512;

    // attn tiles alias the front of stage smem (guarded by the post-loop sync)
    __half* qs  = smh;
    __half* ks_ = qs + 4608;
    __half* vt  = ks_ + 4608;
    __half* ss  = vt + 4608;

    float acc[4][6][4];
    #pragma unroll
    for (int a = 0; a < 4; a++)
        #pragma unroll
        for (int b = 0; b < 6; b++)
            #pragma unroll
            for (int c = 0; c < 4; c++) acc[a][b][c] = 0.f;

    auto fill = [&](int s, int kt) {
        uint32_t As = sb + s * FSTG;
        uint32_t Bs = As + 8192;
        int koff = kt * 64;
        #pragma unroll
        for (int it = 0; it < 4; it++) {              // A: 64 rows x 128B
            int i = tid + it * 128;
            int r = i >> 3, c8 = i & 7;
            cp16(As + r * 128 + ((c8 ^ (r & 7)) << 4), Xp + (size_t)r * 512 + koff + c8 * 8);
        }
        #pragma unroll
        for (int it = 0; it < 12; it++) {             // B: 192 rows (3x64) x 128B
            int i = tid + it * 128;
            int r = i >> 3, c8 = i & 7;
            const __half* src = Wb + (size_t)(r >> 6) * (DD*DD) + (size_t)(r & 63) * 512 + koff + c8 * 8;
            cp16(Bs + r * 128 + ((c8 ^ (r & 7)) << 4), src);
        }
        cp_commit();
    };

    fill(0, 0);
    for (int kt = 0; kt < 8; kt++) {
        asm volatile("cp.async.wait_group 0;" ::: "memory");  // stage kt&1 data landed
        __syncthreads();   // all warps done with compute kt-1 (stage (kt+1)&1 now free)
        if (kt + 1 < 8) fill((kt + 1) & 1, kt + 1);

        char* As = sm + (kt & 1) * FSTG;
        char* Bs = As + 8192;

        #pragma unroll
        for (int ks = 0; ks < 4; ks++) {
            int c0 = ks * 2;
            int sel0 = (c0 ^ g) << 4, sel1 = ((c0 + 1) ^ g) << 4;
            uint32_t af[4][4], bf[6][2];
            #pragma unroll
            for (int im = 0; im < 4; im++) {
                int r = im * 16 + g;
                char* p0 = As + r * 128 + 4 * tg;
                char* p1 = As + (r + 8) * 128 + 4 * tg;
                af[im][0] = *(uint32_t*)(p0 + sel0);
                af[im][1] = *(uint32_t*)(p1 + sel0);
                af[im][2] = *(uint32_t*)(p0 + sel1);
                af[im][3] = *(uint32_t*)(p1 + sel1);
            }
            #pragma unroll
            for (int in = 0; in < 6; in++) {
                int n = wn + in * 8 + g;
                char* p = Bs + n * 128 + 4 * tg;
                bf[in][0] = *(uint32_t*)(p + sel0);
                bf[in][1] = *(uint32_t*)(p + sel1);
            }
            #pragma unroll
            for (int im = 0; im < 4; im++)
                #pragma unroll
                for (int in = 0; in < 6; in++)
                    mma_f16(acc[im][in], af[im][0], af[im][1], af[im][2], af[im][3],
                            bf[in][0], bf[in][1]);
        }
    }
    __syncthreads();   // all warps done reading stage smem before attn tiles alias it

    // epilogue: bias + fp16, route to qs / ks / vt(transposed)
    #pragma unroll
    for (int in = 0; in < 6; in++) {
        int col = wn + in * 8 + 2 * tg;       // even; col,col+1 same region
        int t = col >> 6, lc = col & 63;
        const float* bias = (t == 0) ? bq : (t == 1) ? bk : bv;
        float b0 = bias[h * 64 + lc], b1 = bias[h * 64 + lc + 1];
        #pragma unroll
        for (int im = 0; im < 4; im++) {
            int r0 = im * 16 + g, r1 = r0 + 8;
            __half h00 = __float2half_rn(acc[im][in][0] + b0);
            __half h01 = __float2half_rn(acc[im][in][1] + b1);
            __half h10 = __float2half_rn(acc[im][in][2] + b0);
            __half h11 = __float2half_rn(acc[im][in][3] + b1);
            if (t == 0) {
                __half2 v0; v0.x = h00; v0.y = h01;
                __half2 v1; v1.x = h10; v1.y = h11;
                *(__half2*)(qs + r0 * 72 + lc) = v0;
                *(__half2*)(qs + r1 * 72 + lc) = v1;
            } else if (t == 1) {
                __half2 v0; v0.x = h00; v0.y = h01;
                __half2 v1; v1.x = h10; v1.y = h11;
                *(__half2*)(ks_ + r0 * 72 + lc) = v0;
                *(__half2*)(ks_ + r1 * 72 + lc) = v1;
            } else {
                vt[lc * 72 + r0] = h00; vt[(lc + 1) * 72 + r0] = h01;
                vt[lc * 72 + r1] = h10; vt[(lc + 1) * 72 + r1] = h11;
            }
        }
    }
    __syncthreads();   // q/k/vt tiles complete across all warps

    // ------------- attention (R5 body) -------------
    const int mr = wid * 16;
    float c[8][4];
    #pragma unroll
    for (int in = 0; in < 8; in++)
        #pragma unroll
        for (int j = 0; j < 4; j++) c[in][j] = 0.f;

    // scores = q @ k^T
    #pragma unroll
    for (int ks4 = 0; ks4 < 4; ks4++) {
        int koff = ks4 * 16;
        uint32_t a0 = *(uint32_t*)(qs + (mr + g    ) * 72 + koff + 2 * tg);
        uint32_t a1 = *(uint32_t*)(qs + (mr + g + 8) * 72 + koff + 2 * tg);
        uint32_t a2 = *(uint32_t*)(qs + (mr + g    ) * 72 + koff + 2 * tg + 8);
        uint32_t a3 = *(uint32_t*)(qs + (mr + g + 8) * 72 + koff + 2 * tg + 8);
        #pragma unroll
        for (int in = 0; in < 8; in++) {
            int nr = in * 8 + g;
            uint32_t b0 = *(uint32_t*)(ks_ + nr * 72 + koff + 2 * tg);
            uint32_t b1 = *(uint32_t*)(ks_ + nr * 72 + koff + 2 * tg + 8);
            mma_f16(c[in], a0, a1, a2, a3, b0, b1);
        }
    }

    // softmax (scale 1/8)
    const float scale = 0.125f;
    float mx0 = -1e30f, mx1 = -1e30f;
    #pragma unroll
    for (int in = 0; in < 8; in++) {
        c[in][0] *= scale; c[in][1] *= scale;
        c[in][2] *= scale; c[in][3] *= scale;
        mx0 = fmaxf(mx0, fmaxf(c[in][0], c[in][1]));
        mx1 = fmaxf(mx1, fmaxf(c[in][2], c[in][3]));
    }
    mx0 = fmaxf(mx0, __shfl_xor_sync(0xffffffffu, mx0, 1));
    mx0 = fmaxf(mx0, __shfl_xor_sync(0xffffffffu, mx0, 2));
    mx1 = fmaxf(mx1, __shfl_xor_sync(0xffffffffu, mx1, 1));
    mx1 = fmaxf(mx1, __shfl_xor_sync(0xffffffffu, mx1, 2));

    float s0 = 0.f, s1 = 0.f;
    #pragma unroll
    for (int in = 0; in < 8; in++) {
        c[in][0] = __expf(c[in][0] - mx0); s0 += c[in][0];
        c[in][1] = __expf(c[in][1] - mx0); s0 += c[in][1];
        c[in][2] = __expf(c[in][2] - mx1); s1 += c[in][2];
        c[in][3] = __expf(c[in][3] - mx1); s1 += c[in][3];
    }
    s0 += __shfl_xor_sync(0xffffffffu, s0, 1);
    s0 += __shfl_xor_sync(0xffffffffu, s0, 2);
    s1 += __shfl_xor_sync(0xffffffffu, s1, 1);
    s1 += __shfl_xor_sync(0xffffffffu, s1, 2);
    float inv0 = 1.f / s0, inv1 = 1.f / s1;

    // write P (own warp rows)
    #pragma unroll
    for (int in = 0; in < 8; in++) {
        int col = in * 8 + 2 * tg;
        *(__half2*)(ss + (mr + g    ) * 72 + col) = __floats2half2_rn(c[in][0] * inv0, c[in][1] * inv0);
        *(__half2*)(ss + (mr + g + 8) * 72 + col) = __floats2half2_rn(c[in][2] * inv1, c[in][3] * inv1);
    }
    __syncwarp();

    #pragma unroll
    for (int in = 0; in < 8; in++)
        #pragma unroll
        for (int j = 0; j < 4; j++) c[in][j] = 0.f;

    // out = P @ V   (A = ss[m][m'] own rows, B[k=m'][n=dk] = vt[dk][m'])
    #pragma unroll
    for (int ks4 = 0; ks4 < 4; ks4++) {
        int koff = ks4 * 16;
        uint32_t a0 = *(uint32_t*)(ss + (mr + g    ) * 72 + koff + 2 * tg);
        uint32_t a1 = *(uint32_t*)(ss + (mr + g + 8) * 72 + koff + 2 * tg);
        uint32_t a2 = *(uint32_t*)(ss + (mr + g    ) * 72 + koff + 2 * tg + 8);
        uint32_t a3 = *(uint32_t*)(ss + (mr + g + 8) * 72 + koff + 2 * tg + 8);
        #pragma unroll
        for (int in = 0; in < 8; in++) {
            int nr = in * 8 + g;
            uint32_t b0 = *(uint32_t*)(vt + nr * 72 + koff + 2 * tg);
            uint32_t b1 = *(uint32_t*)(vt + nr * 72 + koff + 2 * tg + 8);
            mma_f16(c[in], a0, a1, a2, a3, b0, b1);
        }
    }

    // stage output tile into ss (own warp rows)
    #pragma unroll
    for (int in = 0; in < 8; in++) {
        int col = in * 8 + 2 * tg;
        *(__half2*)(ss + (mr + g    ) * 72 + col) = __floats2half2_rn(c[in][0], c[in][1]);
        *(__half2*)(ss + (mr + g + 8) * 72 + col) = __floats2half2_rn(c[in][2], c[in][3]);
    }
    __syncthreads();

    // coalesced store: 2 threads per row, 64B each -> full 128B segments
    {
        __half* dst = g_a + ((size_t)bt * 64) * 512 + h * 64;
        int row = tid >> 1, part = tid & 1;
        const uint4* sp = (const uint4*)(ss + row * 72 + part * 32);
        uint4* dp = (uint4*)(dst + (size_t)row * 512 + part * 32);
        dp[0] = sp[0]; dp[1] = sp[1]; dp[2] = sp[2]; dp[3] = sp[3];
    }
}

// ---------------------------------------------------------------------------
// Out-projection GEMM (R13/R15-proven): D[128x128] of out = g_a @ Wo^T + bo
// 3-stage cp.async, BK=64, 4 warps of 64x64, 2 CTAs/SM, one sync per kt.
// ---------------------------------------------------------------------------
#define STG 32768
#define GEMM_SMEM (3*STG)

__device__ __forceinline__ void fill_stage(uint32_t smem_base, int s,
                                           const __half* __restrict__ Ap,
                                           const __half* __restrict__ Bp,
                                           int kt, int tid)
{
    uint32_t As = smem_base + s * STG;
    uint32_t Bs = As + 16384;
    int koff = kt * 64;
    #pragma unroll
    for (int it = 0; it < 8; it++) {
        int i = tid + it * 128;
        int r = i >> 3, c8 = i & 7;
        cp16(As + r * 128 + ((c8 ^ (r & 7)) << 4), Ap + (size_t)r * 512 + koff + c8 * 8);
    }
    #pragma unroll
    for (int it = 0; it < 8; it++) {
        int i = tid + it * 128;
        int r = i >> 3, c8 = i & 7;
        cp16(Bs + r * 128 + ((c8 ^ (r & 7)) << 4), Bp + (size_t)r * 512 + koff + c8 * 8);
    }
    cp_commit();
}

__global__ __launch_bounds__(128, 2)
void gemm_out(const __half* __restrict__ A, const __half* __restrict__ Bw,
              const float* __restrict__ bias, float* __restrict__ out)
{
    extern __shared__ char sm[];
    const int tid = threadIdx.x, wid = tid >> 5, lane = tid & 31;
    const int g = lane >> 2, tg = lane & 3;
    const int n0 = blockIdx.x * 128, m0 = blockIdx.y * 128;
    const int wm = (wid & 1) * 64, wn = (wid >> 1) * 64;

    uint32_t sbase = smem_u32(sm);
    const __half* Ap = A + (size_t)m0 * 512;
    const __half* Bp = Bw + (size_t)n0 * 512;

    float acc[4][8][4];
    #pragma unroll
    for (int a = 0; a < 4; a++)
        #pragma unroll
        for (int b = 0; b < 8; b++)
            #pragma unroll
            for (int c = 0; c < 4; c++) acc[a][b][c] = 0.f;

    fill_stage(sbase, 0, Ap, Bp, 0, tid);
    fill_stage(sbase, 1, Ap, Bp, 1, tid);

    for (int kt = 0; kt < 8; kt++) {
        if (kt < 7) asm volatile("cp.async.wait_group 1;" ::: "memory");
        else        asm volatile("cp.async.wait_group 0;" ::: "memory");
        __syncthreads();
        if (kt + 2 < 8) fill_stage(sbase, (kt + 2) % 3, Ap, Bp, kt + 2, tid);

        char* As = sm + (kt % 3) * STG;
        char* Bs = As + 16384;

        #pragma unroll
        for (int ks = 0; ks < 4; ks++) {
            int c0 = ks * 2;
            int sel0 = (c0 ^ g) << 4, sel1 = ((c0 + 1) ^ g) << 4;
            uint32_t af[4][4], bf[8][2];
            #pragma unroll
            for (int im = 0; im < 4; im++) {
                int r = wm + im * 16 + g;
                char* p0 = As + r * 128 + 4 * tg;
                char* p1 = As + (r + 8) * 128 + 4 * tg;
                af[im][0] = *(uint32_t*)(p0 + sel0);
                af[im][1] = *(uint32_t*)(p1 + sel0);
                af[im][2] = *(uint32_t*)(p0 + sel1);
                af[im][3] = *(uint32_t*)(p1 + sel1);
            }
            #pragma unroll
            for (int in = 0; in < 8; in++) {
                int n = wn + in * 8 + g;
                char* p = Bs + n * 128 + 4 * tg;
                bf[in][0] = *(uint32_t*)(p + sel0);
                bf[in][1] = *(uint32_t*)(p + sel1);
            }
            #pragma unroll
            for (int im = 0; im < 4; im++)
                #pragma unroll
                for (int in = 0; in < 8; in++)
                    mma_f16(acc[im][in], af[im][0], af[im][1], af[im][2], af[im][3],
                            bf[in][0], bf[in][1]);
        }
    }

    #pragma unroll
    for (int im = 0; im < 4; im++) {
        #pragma unroll
        for (int in = 0; in < 8; in++) {
            int col = n0 + wn + in * 8 + 2 * tg;
            float bb0 = bias[col], bb1 = bias[col + 1];
            int r0 = m0 + wm + im * 16 + g;
            float2 v0 = {acc[im][in][0] + bb0, acc[im][in][1] + bb1};
            float2 v1 = {acc[im][in][2] + bb0, acc[im][in][3] + bb1};
            *(float2*)(out + (size_t)r0 * 512 + col) = v0;
            *(float2*)(out + (size_t)(r0 + 8) * 512 + col) = v1;
        }
    }
}

// ---------------------------------------------------------------------------
extern "C" void kernel_launch(void* const* d_in, const int* in_sizes, int n_in,
                              void* d_out, int out_size)
{
    const float* x  = (const float*)d_in[0];
    const float* Wq = (const float*)d_in[1];
    const float* bq = (const float*)d_in[2];
    const float* Wk = (const float*)d_in[3];
    const float* bk = (const float*)d_in[4];
    const float* Wv = (const float*)d_in[5];
    const float* bv = (const float*)d_in[6];
    const float* Wo = (const float*)d_in[7];
    const float* bo = (const float*)d_in[8];
    float* out = (float*)d_out;

    void *pxh, *pwqkv, *pwo, *pa;
    cudaGetSymbolAddress(&pxh,   g_xh);
    cudaGetSymbolAddress(&pwqkv, g_wqkv);
    cudaGetSymbolAddress(&pwo,   g_wo);
    cudaGetSymbolAddress(&pa,    g_a);

    // 1) fp32 -> fp16 conversion of X + all 4 weights in ONE launch
    conv_all<<<XBLK + WBLK, 256>>>((const float4*)x, (uint4*)pxh,
                                   (const float4*)Wq, (const float4*)Wk,
                                   (const float4*)Wv, (const float4*)Wo,
                                   (uint4*)pwqkv, (uint4*)pwo);

    cudaFuncSetAttribute(qkv_attn_kernel, cudaFuncAttributeMaxDynamicSharedMemorySize, FUSED_SMEM);
    cudaFuncSetAttribute(gemm_out, cudaFuncAttributeMaxDynamicSharedMemorySize, GEMM_SMEM);

    // 2) fused QKV projection + attention: one CTA per (bt, h)
    qkv_attn_kernel<<<NBTH, 128, FUSED_SMEM>>>(bq, bk, bv);

    // 3) output projection: out = g_a @ Wo^T + bo
    dim3 go(4, NROWS / 128);
    gemm_out<<<go, 128, GEMM_SMEM>>>((const __half*)pa, (const __half*)pwo, bo, out);
}